// round 10
// baseline (speedup 1.0000x reference)
#include <cuda_runtime.h>
#include <cuda_bf16.h>
#include <cstdint>

#define BSZ 16
#define SSZ 4096
#define HSZ 1024
#define NTOK (BSZ * SSZ)

#define M_CTA 128
#define N_CHUNK 256
#define NCHUNK (HSZ / N_CHUNK)     // 4
#define NSPLIT 2                   // n-chunks split across 2 CTAs per tile
#define BK 32
#define NKSTAGE (HSZ / BK)         // 32 K-stages per chunk
#define NSTAGES_CTA ((NCHUNK / NSPLIT) * NKSTAGE)  // 64 stages per CTA
#define NBUF 4                     // smem buffer ring depth

// gmem tiled blocks (contiguous, pre-swizzled smem images)
#define A_BLK 16384                // 128 rows x 64B  (hi 8K | lo 8K)
#define B_BLK 32768                // 256 rows x 64B  (hi 16K | lo 16K)

// smem layout (bytes)
#define SOFF_SCORE 0               // float[128]
#define SOFF_KEY   512             // float[1024]
#define SOFF_BIAS  4608            // float[1024]
#define SOFF_MBAR  8640            // 4 x 8B mbarriers
#define SOFF_STAGE 9216
#define STG_AHI 0
#define STG_ALO 8192
#define STG_B   16384              // B hi 16K then lo 16K (one gmem block)
#define STAGE_BYTES 49152
#define SMEM_TOTAL (SOFF_STAGE + NBUF * STAGE_BYTES)   // 205824

// ---- scratch (no allocations allowed) ----
__device__ float g_scores_part[NSPLIT * NTOK];
__device__ float g_probs[NTOK];
// A: [tile 512][kstage 32][16KB image]   B: [chunk 4][kstage 32][32KB image]
__device__ __align__(1024) unsigned char g_a[(size_t)512 * 32 * A_BLK]; // 268 MB
__device__ __align__(1024) unsigned char g_b[(size_t)4 * 32 * B_BLK];   // 4 MB

// ---------------------------------------------------------------------------
__device__ __forceinline__ uint32_t s2u(const void* p) {
    return (uint32_t)__cvta_generic_to_shared(p);
}

#define LDMX4(r0, r1, r2, r3, addr) \
    asm volatile("ldmatrix.sync.aligned.m8n8.x4.shared.b16 {%0,%1,%2,%3}, [%4];" \
                 : "=r"(r0), "=r"(r1), "=r"(r2), "=r"(r3) : "r"(addr))

#define MMA16816(d, a, b) \
    asm volatile("mma.sync.aligned.m16n8k16.row.col.f32.bf16.bf16.f32 " \
                 "{%0,%1,%2,%3}, {%4,%5,%6,%7}, {%8,%9}, {%0,%1,%2,%3};" \
                 : "+f"((d)[0]), "+f"((d)[1]), "+f"((d)[2]), "+f"((d)[3]) \
                 : "r"((a)[0]), "r"((a)[1]), "r"((a)[2]), "r"((a)[3]), \
                   "r"((b)[0]), "r"((b)[1]))

__device__ __forceinline__ void mbar_init(uint32_t mbar, uint32_t cnt) {
    asm volatile("mbarrier.init.shared.b64 [%0], %1;" :: "r"(mbar), "r"(cnt) : "memory");
}

__device__ __forceinline__ void mbar_expect_tx(uint32_t mbar, uint32_t bytes) {
    asm volatile("mbarrier.arrive.expect_tx.shared.b64 _, [%0], %1;"
                 :: "r"(mbar), "r"(bytes) : "memory");
}

__device__ __forceinline__ void bulk_g2s(uint32_t sdst, const void* gsrc,
                                         uint32_t bytes, uint32_t mbar) {
    asm volatile("cp.async.bulk.shared::cluster.global.mbarrier::complete_tx::bytes "
                 "[%0], [%1], %2, [%3];"
                 :: "r"(sdst), "l"(gsrc), "r"(bytes), "r"(mbar) : "memory");
}

__device__ __forceinline__ void mbar_wait(uint32_t mbar, uint32_t phase) {
    uint32_t done;
    asm volatile(
        "{\n\t.reg .pred p;\n\t"
        "mbarrier.try_wait.parity.acquire.cta.shared::cta.b64 p, [%1], %2;\n\t"
        "selp.b32 %0, 1, 0, p;\n\t}"
        : "=r"(done) : "r"(mbar), "r"(phase) : "memory");
    if (!done) {
        asm volatile(
            "{\n\t.reg .pred P1;\n\t"
            "WAIT_LOOP_%=:\n\t"
            "mbarrier.try_wait.parity.acquire.cta.shared::cta.b64 P1, [%0], %1, 0x989680;\n\t"
            "@P1 bra.uni WAIT_DONE_%=;\n\t"
            "bra.uni WAIT_LOOP_%=;\n\t"
            "WAIT_DONE_%=:\n\t}"
            :: "r"(mbar), "r"(phase) : "memory");
    }
}

__device__ __forceinline__ float ftanh(float v) {
    float e = __expf(2.0f * v);
    return 1.0f - 2.0f / (e + 1.0f);
}

// ---------------------------------------------------------------------------
// Convert kernel for B (small: 4MB): fp32 -> bf16 hi/lo tiled images.
// Swizzle: 64B rows, 16B chunk c stored at c ^ ((r>>1)&3).
// ---------------------------------------------------------------------------
__global__ __launch_bounds__(256) void convert_b_kernel(const float* __restrict__ W)
{
    int id = blockIdx.x * 256 + threadIdx.x;      // (n, ks, c)
    int c  = id & 3;
    int ks = (id >> 2) & 31;
    int n  = id >> 7;
    const float* src = W + (size_t)n * HSZ + ks * 32 + c * 8;
    float4 v0 = *(const float4*)src;
    float4 v1 = *(const float4*)(src + 4);
    float a[8] = {v0.x, v0.y, v0.z, v0.w, v1.x, v1.y, v1.z, v1.w};

    uint4 hv, lv;
    __nv_bfloat16* hp = (__nv_bfloat16*)&hv;
    __nv_bfloat16* lp = (__nv_bfloat16*)&lv;
    #pragma unroll
    for (int j = 0; j < 8; j++) {
        hp[j] = __float2bfloat16(a[j]);
        lp[j] = __float2bfloat16(a[j] - __bfloat162float(hp[j]));
    }
    int r = n & 255;
    size_t off = ((size_t)(n >> 8) * 32 + ks) * B_BLK
               + (size_t)r * 64 + ((c ^ ((r >> 1) & 3)) << 4);
    *(uint4*)(g_b + off)         = hv;
    *(uint4*)(g_b + off + 16384) = lv;
}

// ---------------------------------------------------------------------------
// Kernel A: fused scores GEMM, bf16x3 split precision on mma.sync HMMA.
// NEW: CTA-local A-conversion prologue — each CTA converts its own tile's
// fp32 x rows into pre-swizzled bf16 hi/lo blocks in g_a (L2-hot), then the
// mainloop bulk-reads them back. NSPLIT siblings convert redundantly with
// identical bytes (race-benign, each CTA self-sufficient). This removes the
// standalone convert_a kernel's serial ~96us; later-wave prologues overlap
// other SMs' mainloops.
// ---------------------------------------------------------------------------
__global__ void __launch_bounds__(512, 1) gemm_scores_kernel(
    const float* __restrict__ x,
    const float* __restrict__ bias, const float* __restrict__ key)
{
    extern __shared__ char smem[];
    const uint32_t sbase = s2u(smem);
    const int tid = threadIdx.x;
    const int wid = tid >> 5;
    const int lid = tid & 31;
    const int wm  = wid & 3;          // warp m index (4)
    const int wn  = wid >> 2;         // warp n index (4)
    const int tile = blockIdx.x >> 1;
    const int half = blockIdx.x & 1;  // n-chunk pair: {0,1} or {2,3}
    const int t0  = tile * M_CTA;

    float* s_score = (float*)(smem + SOFF_SCORE);
    float* s_key   = (float*)(smem + SOFF_KEY);
    float* s_bias  = (float*)(smem + SOFF_BIAS);
    for (int i = tid; i < HSZ; i += 512) {
        s_key[i]  = key[i];
        s_bias[i] = bias[i];
    }
    if (tid < M_CTA) s_score[tid] = 0.0f;
    if (tid == 0) {
        #pragma unroll
        for (int i = 0; i < NBUF; i++) mbar_init(sbase + SOFF_MBAR + i * 8, 1);
    }

    // ---- prologue: convert this tile's A (128 rows x 1024 k) into g_a ----
    {
        const float* xsrc = x + (size_t)t0 * HSZ;
        #pragma unroll 4
        for (int it = 0; it < 32; it++) {
            int slot = tid + it * 512;            // (r, ks, c): 16384 slots
            int c  = slot & 3;
            int ks = (slot >> 2) & 31;
            int r  = slot >> 7;
            const float* src = xsrc + (size_t)r * HSZ + ks * 32 + c * 8;
            float4 v0 = ((const float4*)src)[0];
            float4 v1 = ((const float4*)src)[1];
            float a[8] = {v0.x, v0.y, v0.z, v0.w, v1.x, v1.y, v1.z, v1.w};
            uint4 hv, lv;
            __nv_bfloat16* hp = (__nv_bfloat16*)&hv;
            __nv_bfloat16* lp = (__nv_bfloat16*)&lv;
            #pragma unroll
            for (int j = 0; j < 8; j++) {
                hp[j] = __float2bfloat16(a[j]);
                lp[j] = __float2bfloat16(a[j] - __bfloat162float(hp[j]));
            }
            size_t off = ((size_t)tile * 32 + ks) * A_BLK
                       + (size_t)r * 64 + ((c ^ ((r >> 1) & 3)) << 4);
            *(uint4*)(g_a + off)        = hv;
            *(uint4*)(g_a + off + 8192) = lv;
        }
        // generic-proxy stores must be visible to the async (bulk-DMA) proxy
        asm volatile("fence.proxy.async;" ::: "memory");
    }
    __syncthreads();

    // prologue: stages 0..2
    if (tid == 0) {
        #pragma unroll
        for (int s = 0; s < NBUF - 1; s++) {
            uint32_t mb = sbase + SOFF_MBAR + s * 8;
            mbar_expect_tx(mb, STAGE_BYTES);
            bulk_g2s(sbase + SOFF_STAGE + s * STAGE_BYTES,
                     g_a + ((size_t)tile * 32 + (s & 31)) * A_BLK, A_BLK, mb);
            bulk_g2s(sbase + SOFF_STAGE + s * STAGE_BYTES + STG_B,
                     g_b + ((size_t)(half * 2 + (s >> 5)) * 32 + (s & 31)) * B_BLK,
                     B_BLK, mb);
        }
    }

    // ldmatrix lane geometry
    const int g  = lid >> 3;          // quad-group 0..3
    const int r8 = lid & 7;
    const int a_row  = wm * 32 + (g & 1) * 8 + r8;   // + i*16
    const int a_kh   = g >> 1;                       // k8-half
    const int b_rowb = wn * 64 + (g >> 1) * 8 + r8;  // + nh*32 + p*16
    const int b_kh   = g & 1;
    const int a_xm   = (a_row  >> 1) & 3;            // xor mask (invariant to +16/+32)
    const int b_xm   = (b_rowb >> 1) & 3;

    float acc[2][8][4];
    float score_p[2][2];

    for (int gs = 0; gs < NSTAGES_CTA; gs++) {
        const int ks = gs & 31;
        const uint32_t stg = sbase + SOFF_STAGE + (uint32_t)(gs & 3) * STAGE_BYTES;

        if (ks == 0) {
            #pragma unroll
            for (int i = 0; i < 2; i++)
                #pragma unroll
                for (int j = 0; j < 8; j++)
                    #pragma unroll
                    for (int c = 0; c < 4; c++) acc[i][j][c] = 0.0f;
        }

        mbar_wait(sbase + SOFF_MBAR + (gs & 3) * 8, (gs >> 2) & 1);

        // issue stage gs+3 into the buffer freed at stage gs-1
        if (tid == 0 && gs + 3 < NSTAGES_CTA) {
            const int s = gs + 3;
            uint32_t mb = sbase + SOFF_MBAR + (s & 3) * 8;
            mbar_expect_tx(mb, STAGE_BYTES);
            bulk_g2s(sbase + SOFF_STAGE + (uint32_t)(s & 3) * STAGE_BYTES,
                     g_a + ((size_t)tile * 32 + (s & 31)) * A_BLK, A_BLK, mb);
            bulk_g2s(sbase + SOFF_STAGE + (uint32_t)(s & 3) * STAGE_BYTES + STG_B,
                     g_b + ((size_t)(half * 2 + (s >> 5)) * 32 + (s & 31)) * B_BLK,
                     B_BLK, mb);
        }

        #pragma unroll
        for (int k16 = 0; k16 < 2; k16++) {
            uint32_t ah[2][4], al[2][4];
            const uint32_t a_csw = (uint32_t)(((k16 * 2 + a_kh) ^ a_xm) << 4);
            #pragma unroll
            for (int i = 0; i < 2; i++) {
                uint32_t off = (uint32_t)((a_row + i * 16) << 6) + a_csw;
                LDMX4(ah[i][0], ah[i][1], ah[i][2], ah[i][3], stg + STG_AHI + off);
                LDMX4(al[i][0], al[i][1], al[i][2], al[i][3], stg + STG_ALO + off);
            }
            const uint32_t b_csw = (uint32_t)(((k16 * 2 + b_kh) ^ b_xm) << 4);
            #pragma unroll
            for (int nh = 0; nh < 2; nh++) {
                uint32_t bh[4][2], bl[4][2];
                #pragma unroll
                for (int p = 0; p < 2; p++) {
                    uint32_t off = (uint32_t)((b_rowb + nh * 32 + p * 16) << 6) + b_csw;
                    LDMX4(bh[2*p][0], bh[2*p][1], bh[2*p+1][0], bh[2*p+1][1],
                          stg + STG_B + off);
                    LDMX4(bl[2*p][0], bl[2*p][1], bl[2*p+1][0], bl[2*p+1][1],
                          stg + STG_B + 16384 + off);
                }
                #pragma unroll
                for (int i = 0; i < 2; i++)
                    #pragma unroll
                    for (int j = 0; j < 4; j++) {
                        MMA16816(acc[i][nh * 4 + j], ah[i], bh[j]);  // hi*hi
                        MMA16816(acc[i][nh * 4 + j], ah[i], bl[j]);  // hi*lo
                        MMA16816(acc[i][nh * 4 + j], al[i], bh[j]);  // lo*hi
                    }
            }
        }

        if (ks == 31) {
            // epilogue for this n-chunk: tanh(acc+bias)*key -> score partials
            const int n0 = (half * 2 + (gs >> 5)) * N_CHUNK;
            #pragma unroll
            for (int i = 0; i < 2; i++)
                #pragma unroll
                for (int mh = 0; mh < 2; mh++) score_p[i][mh] = 0.0f;

            #pragma unroll
            for (int i = 0; i < 2; i++)
                #pragma unroll
                for (int j = 0; j < 8; j++)
                    #pragma unroll
                    for (int c = 0; c < 4; c++) {
                        int n = n0 + wn * 64 + j * 8 + (lid & 3) * 2 + (c & 1);
                        float v = ftanh(acc[i][j][c] + s_bias[n]) * s_key[n];
                        score_p[i][c >> 1] += v;
                    }

            #pragma unroll
            for (int i = 0; i < 2; i++)
                #pragma unroll
                for (int mh = 0; mh < 2; mh++) {
                    float v = score_p[i][mh];
                    v += __shfl_xor_sync(0xffffffffu, v, 1);
                    v += __shfl_xor_sync(0xffffffffu, v, 2);
                    if ((lid & 3) == 0) {
                        int m = wm * 32 + i * 16 + mh * 8 + (lid >> 2);
                        atomicAdd(&s_score[m], v);
                    }
                }
        }

        __syncthreads();   // all warps done with this buffer -> reusable
    }

    if (tid < M_CTA) g_scores_part[half * NTOK + t0 + tid] = s_score[tid];
}

// ---------------------------------------------------------------------------
// Kernel B1: per-batch masked softmax over summed partial scores -> probs.
// ---------------------------------------------------------------------------
__global__ __launch_bounds__(256) void softmax_kernel(const int* __restrict__ lengths)
{
    __shared__ float red[256];
    const int b = blockIdx.x;
    const int len = lengths[b];
    const float* sc0 = g_scores_part + b * SSZ;
    const float* sc1 = g_scores_part + NTOK + b * SSZ;
    const int tid = threadIdx.x;

    float m = -1e30f;
    for (int s = tid; s < len; s += 256) m = fmaxf(m, sc0[s] + sc1[s]);
    red[tid] = m;
    __syncthreads();
    for (int o = 128; o > 0; o >>= 1) {
        if (tid < o) red[tid] = fmaxf(red[tid], red[tid + o]);
        __syncthreads();
    }
    m = red[0];
    __syncthreads();

    float sum = 0.f;
    for (int s = tid; s < len; s += 256) sum += expf(sc0[s] + sc1[s] - m);
    red[tid] = sum;
    __syncthreads();
    for (int o = 128; o > 0; o >>= 1) {
        if (tid < o) red[tid] += red[tid + o];
        __syncthreads();
    }
    const float inv = 1.0f / red[0];

    for (int s = tid; s < SSZ; s += 256)
        g_probs[b * SSZ + s] = (s < len) ? expf(sc0[s] + sc1[s] - m) * inv : 0.f;
}

// ---------------------------------------------------------------------------
// Kernel B2: out[b,h] = sum_{s<len} probs[b,s] * x[b,s,h]
// ---------------------------------------------------------------------------
__global__ __launch_bounds__(128) void output_kernel(
    const float* __restrict__ x, const int* __restrict__ lengths,
    float* __restrict__ out)
{
    const int b = blockIdx.y;
    const int h = blockIdx.x * 128 + threadIdx.x;
    const int len = lengths[b];
    const float* xb = x + (size_t)b * SSZ * HSZ + h;
    const float* pb = g_probs + b * SSZ;

    float a0 = 0.f, a1 = 0.f, a2 = 0.f, a3 = 0.f;
    int s = 0;
    for (; s + 4 <= len; s += 4) {
        a0 += pb[s + 0] * xb[(size_t)(s + 0) * HSZ];
        a1 += pb[s + 1] * xb[(size_t)(s + 1) * HSZ];
        a2 += pb[s + 2] * xb[(size_t)(s + 2) * HSZ];
        a3 += pb[s + 3] * xb[(size_t)(s + 3) * HSZ];
    }
    for (; s < len; s++) a0 += pb[s] * xb[(size_t)s * HSZ];

    out[b * HSZ + h] = (a0 + a1) + (a2 + a3);
}

// ---------------------------------------------------------------------------
extern "C" void kernel_launch(void* const* d_in, const int* in_sizes, int n_in,
                              void* d_out, int out_size)
{
    const float* x       = (const float*)d_in[0];
    const int*   lengths = (const int*)  d_in[1];
    const float* W       = (const float*)d_in[2];
    const float* bias    = (const float*)d_in[3];
    const float* key     = (const float*)d_in[4];
    float* out = (float*)d_out;

    cudaFuncSetAttribute(gemm_scores_kernel,
                         cudaFuncAttributeMaxDynamicSharedMemorySize, SMEM_TOTAL);

    convert_b_kernel<<<(HSZ * 32 * 4) / 256, 256>>>(W);

    gemm_scores_kernel<<<(NTOK / M_CTA) * NSPLIT, 512, SMEM_TOTAL>>>(x, bias, key);
    softmax_kernel<<<BSZ, 256>>>(lengths);
    output_kernel<<<dim3(HSZ / 128, BSZ), 128>>>(x, lengths, out);
}

// round 11
// speedup vs baseline: 1.7358x; 1.7358x over previous
#include <cuda_runtime.h>
#include <cuda_bf16.h>
#include <cstdint>

#define BSZ 16
#define SSZ 4096
#define HSZ 1024
#define NTOK (BSZ * SSZ)

#define M_CTA 128
#define N_CHUNK 256
#define NCHUNK (HSZ / N_CHUNK)     // 4
#define NSPLIT 2                   // n-chunks split across 2 CTAs per tile
#define BK 32
#define NKSTAGE (HSZ / BK)         // 32 K-stages per chunk
#define NSTAGES_CTA ((NCHUNK / NSPLIT) * NKSTAGE)  // 64 stages per CTA
#define NBUF 4                     // smem buffer ring depth

// gmem tiled blocks (contiguous, pre-swizzled smem images)
#define A_BLK 16384                // 128 rows x 64B  (hi 8K | lo 8K)
#define B_BLK 32768                // 256 rows x 64B  (hi 16K | lo 16K)

// smem layout (bytes)
#define SOFF_SCORE 0               // float[128]
#define SOFF_KEY   512             // float[1024]
#define SOFF_BIAS  4608            // float[1024]
#define SOFF_MBAR  8640            // 4 x 8B mbarriers
#define SOFF_STAGE 9216
#define STG_AHI 0
#define STG_ALO 8192
#define STG_B   16384              // B hi 16K then lo 16K (one gmem block)
#define STAGE_BYTES 49152
#define SMEM_TOTAL (SOFF_STAGE + NBUF * STAGE_BYTES)   // 205824

// output reduction tiling
#define SCHUNK 128                 // s positions per output block

// ---- scratch (no allocations allowed) ----
__device__ float g_scores_part[NSPLIT * NTOK];
__device__ float g_probs[NTOK];
// A: [tile 512][kstage 32][16KB image]   B: [chunk 4][kstage 32][32KB image]
__device__ __align__(1024) unsigned char g_a[(size_t)512 * 32 * A_BLK]; // 268 MB
__device__ __align__(1024) unsigned char g_b[(size_t)4 * 32 * B_BLK];   // 4 MB

// ---------------------------------------------------------------------------
__device__ __forceinline__ uint32_t s2u(const void* p) {
    return (uint32_t)__cvta_generic_to_shared(p);
}

#define LDMX4(r0, r1, r2, r3, addr) \
    asm volatile("ldmatrix.sync.aligned.m8n8.x4.shared.b16 {%0,%1,%2,%3}, [%4];" \
                 : "=r"(r0), "=r"(r1), "=r"(r2), "=r"(r3) : "r"(addr))

#define MMA16816(d, a, b) \
    asm volatile("mma.sync.aligned.m16n8k16.row.col.f32.bf16.bf16.f32 " \
                 "{%0,%1,%2,%3}, {%4,%5,%6,%7}, {%8,%9}, {%0,%1,%2,%3};" \
                 : "+f"((d)[0]), "+f"((d)[1]), "+f"((d)[2]), "+f"((d)[3]) \
                 : "r"((a)[0]), "r"((a)[1]), "r"((a)[2]), "r"((a)[3]), \
                   "r"((b)[0]), "r"((b)[1]))

__device__ __forceinline__ void mbar_init(uint32_t mbar, uint32_t cnt) {
    asm volatile("mbarrier.init.shared.b64 [%0], %1;" :: "r"(mbar), "r"(cnt) : "memory");
}

__device__ __forceinline__ void mbar_expect_tx(uint32_t mbar, uint32_t bytes) {
    asm volatile("mbarrier.arrive.expect_tx.shared.b64 _, [%0], %1;"
                 :: "r"(mbar), "r"(bytes) : "memory");
}

__device__ __forceinline__ void bulk_g2s(uint32_t sdst, const void* gsrc,
                                         uint32_t bytes, uint32_t mbar) {
    asm volatile("cp.async.bulk.shared::cluster.global.mbarrier::complete_tx::bytes "
                 "[%0], [%1], %2, [%3];"
                 :: "r"(sdst), "l"(gsrc), "r"(bytes), "r"(mbar) : "memory");
}

__device__ __forceinline__ void mbar_wait(uint32_t mbar, uint32_t phase) {
    uint32_t done;
    asm volatile(
        "{\n\t.reg .pred p;\n\t"
        "mbarrier.try_wait.parity.acquire.cta.shared::cta.b64 p, [%1], %2;\n\t"
        "selp.b32 %0, 1, 0, p;\n\t}"
        : "=r"(done) : "r"(mbar), "r"(phase) : "memory");
    if (!done) {
        asm volatile(
            "{\n\t.reg .pred P1;\n\t"
            "WAIT_LOOP_%=:\n\t"
            "mbarrier.try_wait.parity.acquire.cta.shared::cta.b64 P1, [%0], %1, 0x989680;\n\t"
            "@P1 bra.uni WAIT_DONE_%=;\n\t"
            "bra.uni WAIT_LOOP_%=;\n\t"
            "WAIT_DONE_%=:\n\t}"
            :: "r"(mbar), "r"(phase) : "memory");
    }
}

__device__ __forceinline__ float ftanh(float v) {
    float e = __expf(2.0f * v);
    return 1.0f - 2.0f / (e + 1.0f);
}

// ---------------------------------------------------------------------------
// Convert kernels: fp32 -> bf16 hi/lo, written as pre-tiled pre-swizzled
// smem images. Swizzle: 64B rows, 16B chunk c stored at c ^ ((r>>1)&3).
// ---------------------------------------------------------------------------
__global__ __launch_bounds__(256) void convert_a_kernel(const float* __restrict__ x)
{
    int id = blockIdx.x * 256 + threadIdx.x;      // (t, ks, c)
    int c  = id & 3;
    int ks = (id >> 2) & 31;
    int t  = id >> 7;
    const float* src = x + (size_t)t * HSZ + ks * 32 + c * 8;
    float4 v0 = *(const float4*)src;
    float4 v1 = *(const float4*)(src + 4);
    float a[8] = {v0.x, v0.y, v0.z, v0.w, v1.x, v1.y, v1.z, v1.w};

    uint4 hv, lv;
    __nv_bfloat16* hp = (__nv_bfloat16*)&hv;
    __nv_bfloat16* lp = (__nv_bfloat16*)&lv;
    #pragma unroll
    for (int j = 0; j < 8; j++) {
        hp[j] = __float2bfloat16(a[j]);
        lp[j] = __float2bfloat16(a[j] - __bfloat162float(hp[j]));
    }
    int r = t & 127;
    size_t off = ((size_t)(t >> 7) * 32 + ks) * A_BLK
               + (size_t)r * 64 + ((c ^ ((r >> 1) & 3)) << 4);
    *(uint4*)(g_a + off)        = hv;
    *(uint4*)(g_a + off + 8192) = lv;
}

__global__ __launch_bounds__(256) void convert_b_kernel(const float* __restrict__ W)
{
    int id = blockIdx.x * 256 + threadIdx.x;      // (n, ks, c)
    int c  = id & 3;
    int ks = (id >> 2) & 31;
    int n  = id >> 7;
    const float* src = W + (size_t)n * HSZ + ks * 32 + c * 8;
    float4 v0 = *(const float4*)src;
    float4 v1 = *(const float4*)(src + 4);
    float a[8] = {v0.x, v0.y, v0.z, v0.w, v1.x, v1.y, v1.z, v1.w};

    uint4 hv, lv;
    __nv_bfloat16* hp = (__nv_bfloat16*)&hv;
    __nv_bfloat16* lp = (__nv_bfloat16*)&lv;
    #pragma unroll
    for (int j = 0; j < 8; j++) {
        hp[j] = __float2bfloat16(a[j]);
        lp[j] = __float2bfloat16(a[j] - __bfloat162float(hp[j]));
    }
    int r = n & 255;
    size_t off = ((size_t)(n >> 8) * 32 + ks) * B_BLK
               + (size_t)r * 64 + ((c ^ ((r >> 1) & 3)) << 4);
    *(uint4*)(g_b + off)         = hv;
    *(uint4*)(g_b + off + 16384) = lv;
}

// ---------------------------------------------------------------------------
// Kernel A: fused scores GEMM, bf16x3 split precision on mma.sync HMMA.
// N-split across 2 CTAs per tile; cp.async.bulk feeds, 4-deep smem ring.
// ---------------------------------------------------------------------------
__global__ void __launch_bounds__(512, 1) gemm_scores_kernel(
    const float* __restrict__ bias, const float* __restrict__ key)
{
    extern __shared__ char smem[];
    const uint32_t sbase = s2u(smem);
    const int tid = threadIdx.x;
    const int wid = tid >> 5;
    const int lid = tid & 31;
    const int wm  = wid & 3;          // warp m index (4)
    const int wn  = wid >> 2;         // warp n index (4)
    const int tile = blockIdx.x >> 1;
    const int half = blockIdx.x & 1;  // n-chunk pair: {0,1} or {2,3}
    const int t0  = tile * M_CTA;

    float* s_score = (float*)(smem + SOFF_SCORE);
    float* s_key   = (float*)(smem + SOFF_KEY);
    float* s_bias  = (float*)(smem + SOFF_BIAS);
    for (int i = tid; i < HSZ; i += 512) {
        s_key[i]  = key[i];
        s_bias[i] = bias[i];
    }
    if (tid < M_CTA) s_score[tid] = 0.0f;
    if (tid == 0) {
        #pragma unroll
        for (int i = 0; i < NBUF; i++) mbar_init(sbase + SOFF_MBAR + i * 8, 1);
    }
    __syncthreads();

    // prologue: stages 0..2
    if (tid == 0) {
        #pragma unroll
        for (int s = 0; s < NBUF - 1; s++) {
            uint32_t mb = sbase + SOFF_MBAR + s * 8;
            mbar_expect_tx(mb, STAGE_BYTES);
            bulk_g2s(sbase + SOFF_STAGE + s * STAGE_BYTES,
                     g_a + ((size_t)tile * 32 + (s & 31)) * A_BLK, A_BLK, mb);
            bulk_g2s(sbase + SOFF_STAGE + s * STAGE_BYTES + STG_B,
                     g_b + ((size_t)(half * 2 + (s >> 5)) * 32 + (s & 31)) * B_BLK,
                     B_BLK, mb);
        }
    }

    // ldmatrix lane geometry
    const int g  = lid >> 3;          // quad-group 0..3
    const int r8 = lid & 7;
    const int a_row  = wm * 32 + (g & 1) * 8 + r8;   // + i*16
    const int a_kh   = g >> 1;                       // k8-half
    const int b_rowb = wn * 64 + (g >> 1) * 8 + r8;  // + nh*32 + p*16
    const int b_kh   = g & 1;
    const int a_xm   = (a_row  >> 1) & 3;            // xor mask (invariant to +16/+32)
    const int b_xm   = (b_rowb >> 1) & 3;

    float acc[2][8][4];
    float score_p[2][2];

    for (int gs = 0; gs < NSTAGES_CTA; gs++) {
        const int ks = gs & 31;
        const uint32_t stg = sbase + SOFF_STAGE + (uint32_t)(gs & 3) * STAGE_BYTES;

        if (ks == 0) {
            #pragma unroll
            for (int i = 0; i < 2; i++)
                #pragma unroll
                for (int j = 0; j < 8; j++)
                    #pragma unroll
                    for (int c = 0; c < 4; c++) acc[i][j][c] = 0.0f;
        }

        mbar_wait(sbase + SOFF_MBAR + (gs & 3) * 8, (gs >> 2) & 1);

        // issue stage gs+3 into the buffer freed at stage gs-1
        if (tid == 0 && gs + 3 < NSTAGES_CTA) {
            const int s = gs + 3;
            uint32_t mb = sbase + SOFF_MBAR + (s & 3) * 8;
            mbar_expect_tx(mb, STAGE_BYTES);
            bulk_g2s(sbase + SOFF_STAGE + (uint32_t)(s & 3) * STAGE_BYTES,
                     g_a + ((size_t)tile * 32 + (s & 31)) * A_BLK, A_BLK, mb);
            bulk_g2s(sbase + SOFF_STAGE + (uint32_t)(s & 3) * STAGE_BYTES + STG_B,
                     g_b + ((size_t)(half * 2 + (s >> 5)) * 32 + (s & 31)) * B_BLK,
                     B_BLK, mb);
        }

        #pragma unroll
        for (int k16 = 0; k16 < 2; k16++) {
            uint32_t ah[2][4], al[2][4];
            const uint32_t a_csw = (uint32_t)(((k16 * 2 + a_kh) ^ a_xm) << 4);
            #pragma unroll
            for (int i = 0; i < 2; i++) {
                uint32_t off = (uint32_t)((a_row + i * 16) << 6) + a_csw;
                LDMX4(ah[i][0], ah[i][1], ah[i][2], ah[i][3], stg + STG_AHI + off);
                LDMX4(al[i][0], al[i][1], al[i][2], al[i][3], stg + STG_ALO + off);
            }
            const uint32_t b_csw = (uint32_t)(((k16 * 2 + b_kh) ^ b_xm) << 4);
            #pragma unroll
            for (int nh = 0; nh < 2; nh++) {
                uint32_t bh[4][2], bl[4][2];
                #pragma unroll
                for (int p = 0; p < 2; p++) {
                    uint32_t off = (uint32_t)((b_rowb + nh * 32 + p * 16) << 6) + b_csw;
                    LDMX4(bh[2*p][0], bh[2*p][1], bh[2*p+1][0], bh[2*p+1][1],
                          stg + STG_B + off);
                    LDMX4(bl[2*p][0], bl[2*p][1], bl[2*p+1][0], bl[2*p+1][1],
                          stg + STG_B + 16384 + off);
                }
                #pragma unroll
                for (int i = 0; i < 2; i++)
                    #pragma unroll
                    for (int j = 0; j < 4; j++) {
                        MMA16816(acc[i][nh * 4 + j], ah[i], bh[j]);  // hi*hi
                        MMA16816(acc[i][nh * 4 + j], ah[i], bl[j]);  // hi*lo
                        MMA16816(acc[i][nh * 4 + j], al[i], bh[j]);  // lo*hi
                    }
            }
        }

        if (ks == 31) {
            // epilogue for this n-chunk: tanh(acc+bias)*key -> score partials
            const int n0 = (half * 2 + (gs >> 5)) * N_CHUNK;
            #pragma unroll
            for (int i = 0; i < 2; i++)
                #pragma unroll
                for (int mh = 0; mh < 2; mh++) score_p[i][mh] = 0.0f;

            #pragma unroll
            for (int i = 0; i < 2; i++)
                #pragma unroll
                for (int j = 0; j < 8; j++)
                    #pragma unroll
                    for (int c = 0; c < 4; c++) {
                        int n = n0 + wn * 64 + j * 8 + (lid & 3) * 2 + (c & 1);
                        float v = ftanh(acc[i][j][c] + s_bias[n]) * s_key[n];
                        score_p[i][c >> 1] += v;
                    }

            #pragma unroll
            for (int i = 0; i < 2; i++)
                #pragma unroll
                for (int mh = 0; mh < 2; mh++) {
                    float v = score_p[i][mh];
                    v += __shfl_xor_sync(0xffffffffu, v, 1);
                    v += __shfl_xor_sync(0xffffffffu, v, 2);
                    if ((lid & 3) == 0) {
                        int m = wm * 32 + i * 16 + mh * 8 + (lid >> 2);
                        atomicAdd(&s_score[m], v);
                    }
                }
        }

        __syncthreads();   // all warps done with this buffer -> reusable
    }

    if (tid < M_CTA) g_scores_part[half * NTOK + t0 + tid] = s_score[tid];
}

// ---------------------------------------------------------------------------
// Kernel B1: per-batch masked softmax over summed partial scores -> probs.
// ---------------------------------------------------------------------------
__global__ __launch_bounds__(256) void softmax_kernel(const int* __restrict__ lengths)
{
    __shared__ float red[256];
    const int b = blockIdx.x;
    const int len = lengths[b];
    const float* sc0 = g_scores_part + b * SSZ;
    const float* sc1 = g_scores_part + NTOK + b * SSZ;
    const int tid = threadIdx.x;

    float m = -1e30f;
    for (int s = tid; s < len; s += 256) m = fmaxf(m, sc0[s] + sc1[s]);
    red[tid] = m;
    __syncthreads();
    for (int o = 128; o > 0; o >>= 1) {
        if (tid < o) red[tid] = fmaxf(red[tid], red[tid + o]);
        __syncthreads();
    }
    m = red[0];
    __syncthreads();

    float sum = 0.f;
    for (int s = tid; s < len; s += 256) sum += expf(sc0[s] + sc1[s] - m);
    red[tid] = sum;
    __syncthreads();
    for (int o = 128; o > 0; o >>= 1) {
        if (tid < o) red[tid] += red[tid + o];
        __syncthreads();
    }
    const float inv = 1.0f / red[0];

    for (int s = tid; s < SSZ; s += 256)
        g_probs[b * SSZ + s] = (s < len) ? expf(sc0[s] + sc1[s] - m) * inv : 0.f;
}

// ---------------------------------------------------------------------------
// Kernel B2a: zero the output (harness poisons it to 0xAA).
// ---------------------------------------------------------------------------
__global__ __launch_bounds__(256) void output_init_kernel(float* __restrict__ out)
{
    out[blockIdx.x * 256 + threadIdx.x] = 0.0f;
}

// ---------------------------------------------------------------------------
// Kernel B2b: out[b,h] += sum_{s in chunk, s<len} probs[b,s] * x[b,s,h]
// Grid (S/SCHUNK, B), 256 threads; each thread owns 4 contiguous h (float4
// coalesced loads), loops over the s-chunk, one atomicAdd per h.
// 512 blocks -> full-chip DRAM parallelism (vs 128 latency-bound before).
// ---------------------------------------------------------------------------
__global__ __launch_bounds__(256) void output_kernel(
    const float* __restrict__ x, const int* __restrict__ lengths,
    float* __restrict__ out)
{
    const int b  = blockIdx.y;
    const int s0 = blockIdx.x * SCHUNK;
    const int len = lengths[b];
    if (s0 >= len) return;
    const int ns = min(SCHUNK, len - s0);

    const int h4 = threadIdx.x * 4;
    const float4* xb = (const float4*)(x + ((size_t)b * SSZ + s0) * HSZ + h4);
    const float* pb = g_probs + b * SSZ + s0;

    float a0 = 0.f, a1 = 0.f, a2 = 0.f, a3 = 0.f;
    for (int s = 0; s < ns; s++) {
        float p = pb[s];
        float4 v = xb[(size_t)s * (HSZ / 4)];
        a0 += p * v.x;
        a1 += p * v.y;
        a2 += p * v.z;
        a3 += p * v.w;
    }
    float* o = out + b * HSZ + h4;
    atomicAdd(o + 0, a0);
    atomicAdd(o + 1, a1);
    atomicAdd(o + 2, a2);
    atomicAdd(o + 3, a3);
}

// ---------------------------------------------------------------------------
extern "C" void kernel_launch(void* const* d_in, const int* in_sizes, int n_in,
                              void* d_out, int out_size)
{
    const float* x       = (const float*)d_in[0];
    const int*   lengths = (const int*)  d_in[1];
    const float* W       = (const float*)d_in[2];
    const float* bias    = (const float*)d_in[3];
    const float* key     = (const float*)d_in[4];
    float* out = (float*)d_out;

    cudaFuncSetAttribute(gemm_scores_kernel,
                         cudaFuncAttributeMaxDynamicSharedMemorySize, SMEM_TOTAL);

    convert_a_kernel<<<(NTOK * 32 * 4) / 256, 256>>>(x);
    convert_b_kernel<<<(HSZ * 32 * 4) / 256, 256>>>(W);

    gemm_scores_kernel<<<(NTOK / M_CTA) * NSPLIT, 512, SMEM_TOTAL>>>(bias, key);
    softmax_kernel<<<BSZ, 256>>>(lengths);
    output_init_kernel<<<(BSZ * HSZ) / 256, 256>>>(out);
    output_kernel<<<dim3(SSZ / SCHUNK, BSZ), 256>>>(x, lengths, out);
}